// round 1
// baseline (speedup 1.0000x reference)
#include <cuda_runtime.h>
#include <math.h>

// ---------------- problem constants ----------------
#define NUM_TOKENS   8192
#define NUM_HEADS    32
#define NUM_KV_HEADS 8
#define HEAD_SIZE    128
#define NUM_SLOTS    16384            // NUM_BLOCKS * BLOCK_SIZE
#define ROW_F4       1536             // 6144 floats per qkv row / 4

#define Q_ELEMS      ((size_t)NUM_TOKENS * NUM_HEADS * HEAD_SIZE)      // 33554432
#define K_ELEMS      ((size_t)NUM_TOKENS * NUM_KV_HEADS * HEAD_SIZE)   // 8388608
#define CACHE_PART_F4 ((size_t)NUM_SLOTS * NUM_KV_HEADS * HEAD_SIZE / 4) // 4194304

#define RMS_EPS 1e-6f

// ---------------- device scratch (no allocs allowed) ----------------
__device__ float        g_inv_freq[64];
__device__ unsigned int g_flags[NUM_SLOTS];

// ---------------- tiny setup kernels ----------------
__global__ void init_inv_freq_kernel() {
    int i = threadIdx.x;            // 0..63
    // inv_freq[i] = 10000^(-2i/128), computed in double once per launch
    double e = -(double)(2 * i) / 128.0;
    g_inv_freq[i] = (float)exp2(e * 13.287712379549449);   // log2(10000)
}

__global__ void set_flags_kernel(const int* __restrict__ slot_mapping, int n) {
    int i = blockIdx.x * blockDim.x + threadIdx.x;
    if (i < n) g_flags[slot_mapping[i]] = 1u;
}

// Copy kv_cache input -> output for slots that will NOT be overwritten.
// One block per slot; 256 threads move 2 x 256 float4 (k part + v part).
__global__ void copy_unwritten_cache_kernel(const float4* __restrict__ src,
                                            float4* __restrict__ dst) {
    int slot = blockIdx.x;
    if (g_flags[slot]) return;
    size_t o0 = (size_t)slot * 256 + threadIdx.x;  // k part
    size_t o1 = o0 + CACHE_PART_F4;                // v part
    dst[o0] = src[o0];
    dst[o1] = src[o1];
}

// ---------------- fused norm + rope helper ----------------
__device__ __forceinline__ float4 norm_rope(float4 x, const float4* __restrict__ w4,
                                            int lane, const float* s_cos,
                                            const float* s_sin) {
    // RMS over the full 128-elem head vector (warp-wide)
    float ss = x.x * x.x + x.y * x.y + x.z * x.z + x.w * x.w;
#pragma unroll
    for (int o = 16; o >= 1; o >>= 1) ss += __shfl_xor_sync(0xffffffffu, ss, o);
    float r = rsqrtf(ss * (1.0f / 128.0f) + RMS_EPS);

    float4 w = w4[lane];
    float4 n;
    n.x = x.x * r * w.x;
    n.y = x.y * r * w.y;
    n.z = x.z * r * w.z;
    n.w = x.w * r * w.w;

    // NeoX pairing: element j pairs with j^64  -> lane l pairs with lane l^16
    float px = __shfl_xor_sync(0xffffffffu, n.x, 16);
    float py = __shfl_xor_sync(0xffffffffu, n.y, 16);
    float pz = __shfl_xor_sync(0xffffffffu, n.z, 16);
    float pw = __shfl_xor_sync(0xffffffffu, n.w, 16);

    int fi = (lane & 15) << 2;
    float c0 = s_cos[fi + 0], c1 = s_cos[fi + 1], c2 = s_cos[fi + 2], c3 = s_cos[fi + 3];
    float s0 = s_sin[fi + 0], s1 = s_sin[fi + 1], s2 = s_sin[fi + 2], s3 = s_sin[fi + 3];

    float4 o;
    if (lane < 16) {      // first half: x1*cos - x2*sin
        o.x = n.x * c0 - px * s0;
        o.y = n.y * c1 - py * s1;
        o.z = n.z * c2 - pz * s2;
        o.w = n.w * c3 - pw * s3;
    } else {              // second half: x2*cos + x1*sin
        o.x = n.x * c0 + px * s0;
        o.y = n.y * c1 + py * s1;
        o.z = n.z * c2 + pz * s2;
        o.w = n.w * c3 + pw * s3;
    }
    return o;
}

// ---------------- main fused kernel: one block per token ----------------
__global__ __launch_bounds__(512, 2)
void qknorm_rope_cache_kernel(const float* __restrict__ qkv,
                              const int* __restrict__ positions,
                              const int* __restrict__ slot_mapping,
                              const float* __restrict__ q_weight,
                              const float* __restrict__ k_weight,
                              float* __restrict__ out) {
    __shared__ float s_cos[64];
    __shared__ float s_sin[64];

    const int t   = blockIdx.x;
    const int tid = threadIdx.x;

    const int pos  = positions[t];
    const int slot = slot_mapping[t];

    if (tid < 64) {
        float phase = (float)pos * g_inv_freq[tid];
        float s, c;
        sincosf(phase, &s, &c);
        s_cos[tid] = c;
        s_sin[tid] = s;
    }
    __syncthreads();

    const int warp = tid >> 5;
    const int lane = tid & 31;

    const float4* row = (const float4*)(qkv + (size_t)t * 6144);
    const float4* qw4 = (const float4*)q_weight;
    const float4* kw4 = (const float4*)k_weight;

    float4* q_out     = (float4*)(out);
    float4* k_out     = (float4*)(out + Q_ELEMS);
    float4* v_out     = (float4*)(out + Q_ELEMS + K_ELEMS);
    float4* cache_out = (float4*)(out + Q_ELEMS + 2 * K_ELEMS);

#pragma unroll
    for (int iter = 0; iter < 3; iter++) {
        int unit = warp + (iter << 4);     // 0..47
        if (unit < 32) {
            // ---- Q head ----
            int h = unit;
            float4 x = row[h * 32 + lane];
            float4 o = norm_rope(x, qw4, lane, s_cos, s_sin);
            q_out[(size_t)t * 1024 + h * 32 + lane] = o;
        } else if (unit < 40) {
            // ---- K head ----
            int h = unit - 32;
            float4 x = row[1024 + h * 32 + lane];
            float4 o = norm_rope(x, kw4, lane, s_cos, s_sin);
            size_t idx = (size_t)t * 256 + h * 32 + lane;
            k_out[idx] = o;
            cache_out[(size_t)slot * 256 + h * 32 + lane] = o;          // k part
        } else {
            // ---- V head (plain copy) ----
            int h = unit - 40;
            float4 x = row[1280 + h * 32 + lane];
            size_t idx = (size_t)t * 256 + h * 32 + lane;
            v_out[idx] = x;
            cache_out[CACHE_PART_F4 + (size_t)slot * 256 + h * 32 + lane] = x;  // v part
        }
    }
}

// ---------------- launch ----------------
extern "C" void kernel_launch(void* const* d_in, const int* in_sizes, int n_in,
                              void* d_out, int out_size) {
    const float* qkv          = (const float*)d_in[0];
    const int*   positions    = (const int*)d_in[1];
    const int*   slot_mapping = (const int*)d_in[2];
    const float* q_weight     = (const float*)d_in[3];
    const float* k_weight     = (const float*)d_in[4];
    const float* kv_cache     = (const float*)d_in[5];
    float*       out          = (float*)d_out;

    // reset slot flags (capturable memset node)
    void* flags_ptr = nullptr;
    cudaGetSymbolAddress(&flags_ptr, g_flags);
    cudaMemsetAsync(flags_ptr, 0, sizeof(unsigned int) * NUM_SLOTS);

    init_inv_freq_kernel<<<1, 64>>>();
    set_flags_kernel<<<(NUM_TOKENS + 255) / 256, 256>>>(slot_mapping, NUM_TOKENS);

    float* cache_out = out + Q_ELEMS + 2 * K_ELEMS;
    copy_unwritten_cache_kernel<<<NUM_SLOTS, 256>>>((const float4*)kv_cache,
                                                    (float4*)cache_out);

    qknorm_rope_cache_kernel<<<NUM_TOKENS, 512>>>(qkv, positions, slot_mapping,
                                                  q_weight, k_weight, out);
}